// round 8
// baseline (speedup 1.0000x reference)
#include <cuda_runtime.h>
#include <cuda_bf16.h>

#define EPB 64                 // elements per block (2 per thread)
#define BLK 96                 // 3 warps: warp w handles matrix w for 64 elems
#define NSWEEP 4

typedef unsigned long long u64;

// packed f32x2 helpers (sm_100a FFMA2 pipe). All packed math via fma.rn.f32x2.
__device__ __forceinline__ u64 pk2(float lo, float hi) {
    u64 r; asm("mov.b64 %0, {%1, %2};" : "=l"(r) : "f"(lo), "f"(hi)); return r;
}
__device__ __forceinline__ void up2(u64 p, float& lo, float& hi) {
    asm("mov.b64 {%0, %1}, %2;" : "=f"(lo), "=f"(hi) : "l"(p));
}
__device__ __forceinline__ u64 ffma2(u64 a, u64 b, u64 c) {
    u64 d; asm("fma.rn.f32x2 %0, %1, %2, %3;" : "=l"(d) : "l"(a), "l"(b), "l"(c));
    return d;
}
__device__ __forceinline__ u64 fneg2(u64 a) { return a ^ 0x8000000080000000ULL; }
#define PK0   0x0000000000000000ULL
#define PK1   0x3f8000003f800000ULL   // {1.0f, 1.0f}
#define PKM1  0xbf800000bf800000ULL   // {-1.0f, -1.0f}
#define PKH   0x3f0000003f000000ULL   // {0.5f, 0.5f}
#define PKMH  0xbf000000bf000000ULL   // {-0.5f, -0.5f}
__device__ __forceinline__ u64 fmul2(u64 a, u64 b) { return ffma2(a, b, PK0); }
__device__ __forceinline__ u64 fadd2(u64 a, u64 b) { return ffma2(a, PK1, b); }
__device__ __forceinline__ u64 fsub2(u64 a, u64 b) { return ffma2(b, PKM1, a); }

// upper-triangle index, j<k, matches Gell-Mann sym/antisym ordering
__device__ __forceinline__ int uidx(int j, int k) {
    return j * 8 - (j * (j + 1)) / 2 + (k - j - 1);
}

// scalar rotation parameters for one half (2x2 pivot [[dp,a],[conj(a),dq]])
__device__ __forceinline__ void rotparam(float v2, float delta, float b2,
                                         float ar, float ai,
                                         float& c, float& wr, float& wi, float& sv) {
    bool ok = v2 > 1e-36f;
    float vv = sqrtf(v2);
    sv = copysignf(vv, delta);
    float u0 = delta + sv;
    float n2 = fmaf(u0, u0, b2);
    float ninv = rsqrtf(ok ? n2 : 1.f);
    c  = ok ? u0 * ninv : 1.f;
    wr = ok ? ar * ninv : 0.f;
    wi = ok ? -ai * ninv : 0.f;
}

__global__ __launch_bounds__(BLK)
void bes_kernel(const float* __restrict__ rho,
                const int* __restrict__ rank0p,
                const int* __restrict__ rank1p,
                float* __restrict__ out, int n)
{
    __shared__ float sv[EPB][65];    // staged input, padded rows
    __shared__ float ex[EPB][4];     // paMin, paMax, pcMin, pcMax exchange

    const int tid  = threadIdx.x;
    const int mat  = tid >> 5;       // warp id = matrix (0:H 1:PT_A 2:PT_C)
    const int e    = tid & 31;       // lo element; hi element = e + 32
    const int base = blockIdx.x * EPB;

    const int n0 = 8 - rank0p[0];
    const int n1 = 8 - rank1p[0];

    for (int i = tid; i < EPB * 63; i += BLK) {
        int t = i / 63;
        if (base + t < n) sv[t][i - t * 63] = rho[(long long)base * 63 + i];
    }
    __syncthreads();

    const float* vL = sv[e];
    const float* vH = sv[e + 32];

    // --- normalize (per half) ---
    float ssL = 0.f, ssH = 0.f;
#pragma unroll
    for (int i = 0; i < 63; ++i) { ssL += vL[i] * vL[i]; ssH += vH[i] * vH[i]; }
    const float invL = rsqrtf(ssL);
    const float invH = rsqrtf(ssH);

    // --- diagonal of H (traceless; I/8 folded out; PT preserves diagonal) ---
    const float CL[8] = {0.f, 1.0f, 0.57735026919f, 0.40824829046f,
                         0.31622776601f, 0.25819888975f, 0.21821789023f, 0.18898223650f};
    float fL[8], fH[8];
    fL[0] = 0.f; fH[0] = 0.f;
#pragma unroll
    for (int l = 1; l < 8; ++l) {
        fL[l] = CL[l] * vL[55 + l] * invL;
        fH[l] = CL[l] * vH[55 + l] * invH;
    }
    u64 d8p[8];
    {
        float sufL = 0.f, sufH = 0.f;
        float dL[8], dHh[8];
#pragma unroll
        for (int j = 7; j >= 0; --j) {
            dL[j]  = sufL - (float)j * fL[j]; sufL += fL[j];
            dHh[j] = sufH - (float)j * fH[j]; sufH += fH[j];
        }
#pragma unroll
        for (int j = 0; j < 8; ++j) d8p[j] = pk2(dL[j], dHh[j]);
    }

    // --- build packed upper triangle: branchless PT permutation ---
    const int m  = (mat == 0) ? 7 : (mat == 1 ? 4 : 6);
    const int mc = 7 ^ m;
    u64 ur[28], ui[28];
#pragma unroll
    for (int j = 0; j < 8; ++j) {
#pragma unroll
        for (int k = j + 1; k < 8; ++k) {
            int r2 = (j & m) | (k & mc);
            int c2 = (k & m) | (j & mc);
            int rr = r2 < c2 ? r2 : c2;
            int cc = r2 < c2 ? c2 : r2;
            int m2 = uidx(rr, cc);
            float sgn = (r2 < c2) ? -1.f : 1.f;
            float reL = vL[m2] * invL, imL = sgn * vL[28 + m2] * invL;
            float reH = vH[m2] * invH, imH = sgn * vH[28 + m2] * invH;
            ur[uidx(j, k)] = pk2(reL, reH);
            ui[uidx(j, k)] = pk2(imL, imH);
        }
    }

    // --- cyclic complex Hermitian Jacobi, direct-eigenvector rotation ---
    // param chain scalar per half (2-way ILP); update loop fully packed f32x2.
#pragma unroll 1
    for (int sweep = 0; sweep < NSWEEP; ++sweep) {
#pragma unroll
        for (int p = 0; p < 8; ++p) {
#pragma unroll
            for (int q = p + 1; q < 8; ++q) {
                const int ipq = uidx(p, q);
                u64 rP = ur[ipq], iP = ui[ipq];
                u64 b2P = ffma2(rP, rP, fmul2(iP, iP));
                u64 dpP = d8p[p], dqP = d8p[q];
                u64 deltaP = ffma2(dqP, PKMH, fmul2(dpP, PKH));
                u64 mmP    = ffma2(dqP, PKH,  fmul2(dpP, PKH));
                u64 v2P = ffma2(deltaP, deltaP, b2P);

                float v2a, v2b, da, db, b2a, b2b, ra, rb, ia, ib;
                up2(v2P, v2a, v2b); up2(deltaP, da, db); up2(b2P, b2a, b2b);
                up2(rP, ra, rb); up2(iP, ia, ib);
                float ca, wra, wia, sva, cb, wrb, wib, svb;
                rotparam(v2a, da, b2a, ra, ia, ca, wra, wia, sva);
                rotparam(v2b, db, b2b, rb, ib, cb, wrb, wib, svb);
                u64 cP  = pk2(ca, cb);
                u64 wrP = pk2(wra, wrb);
                u64 wiP = pk2(wia, wib);
                u64 svP = pk2(sva, svb);
                u64 wrN = fneg2(wrP), wiN = fneg2(wiP);

                d8p[p] = ffma2(svP, PK1,  mmP);
                d8p[q] = ffma2(svP, PKM1, mmP);
                ur[ipq] = PK0; ui[ipq] = PK0;

#pragma unroll
                for (int k = 0; k < 8; ++k) {
                    if (k == p || k == q) continue;
                    u64 xr, xi, yr, yi;
                    if (k < p) { xr = ur[uidx(k, p)]; xi = ui[uidx(k, p)]; }
                    else       { xr = ur[uidx(p, k)]; xi = fneg2(ui[uidx(p, k)]); }
                    if (k < q) { yr = ur[uidx(k, q)]; yi = ui[uidx(k, q)]; }
                    else       { yr = ur[uidx(q, k)]; yi = fneg2(ui[uidx(q, k)]); }
                    // nx = c*x + w*y ; ny = c*y - conj(w)*x  (c real, w = conj(a)/nrm)
                    u64 nxr = ffma2(wiN, yi, ffma2(wrP, yr, fmul2(cP, xr)));
                    u64 nxi = ffma2(wiP, yr, ffma2(wrP, yi, fmul2(cP, xi)));
                    u64 nyr = ffma2(wrN, xr, ffma2(wiN, xi, fmul2(cP, yr)));
                    u64 nyi = ffma2(wrN, xi, ffma2(wiP, xr, fmul2(cP, yi)));
                    if (k < p) { ur[uidx(k, p)] = nxr; ui[uidx(k, p)] = nxi; }
                    else       { ur[uidx(p, k)] = nxr; ui[uidx(p, k)] = fneg2(nxi); }
                    if (k < q) { ur[uidx(k, q)] = nyr; ui[uidx(k, q)] = nyi; }
                    else       { ur[uidx(q, k)] = nyr; ui[uidx(q, k)] = fneg2(nyi); }
                }
            }
        }
    }

    // --- unpack eigenvalues ---
    float d8s[2][8];
#pragma unroll
    for (int i = 0; i < 8; ++i) up2(d8p[i], d8s[0][i], d8s[1][i]);

    if (mat != 0) {
#pragma unroll
        for (int h = 0; h < 2; ++h) {
            float mn = d8s[h][0], mx = d8s[h][0];
#pragma unroll
            for (int i = 1; i < 8; ++i) { mn = fminf(mn, d8s[h][i]); mx = fmaxf(mx, d8s[h][i]); }
            ex[e + 32 * h][(mat - 1) * 2 + 0] = mn;
            ex[e + 32 * h][(mat - 1) * 2 + 1] = mx;
        }
    }
    __syncthreads();

    if (mat == 0) {
#pragma unroll 1
        for (int h = 0; h < 2; ++h) {
            const int el = e + 32 * h;
            if (base + el >= n) continue;
            float* d8 = d8s[h];
            // bubble sorting network, ascending
#pragma unroll
            for (int i = 0; i < 7; ++i)
#pragma unroll
                for (int j = 0; j < 7 - i; ++j) {
                    float lo = fminf(d8[j], d8[j + 1]);
                    float hi = fmaxf(d8[j], d8[j + 1]);
                    d8[j] = lo; d8[j + 1] = hi;
                }
            float l0 = d8[0], l7 = d8[7];
            float sumS0 = 0.f, sumL0 = 0.f, sumS1 = 0.f, sumL1 = 0.f;
#pragma unroll
            for (int i = 0; i < 8; ++i) {
                if (i < n0)      sumS0 += d8[i];
                if (i >= 8 - n0) sumL0 += d8[i];
                if (i < n1)      sumS1 += d8[i];
                if (i >= 8 - n1) sumL1 += d8[i];
            }
            float paMin = ex[el][0], paMax = ex[el][1];
            float pcMin = ex[el][2], pcMax = ex[el][3];

            const float beta0 = 1.f / (1.f - 8.f * (l0 + 0.125f));
            const float beta1 = 1.f / (1.f - 8.f * (l7 + 0.125f));

            float loss0 = beta0 * (beta0 >= 0.f ? sumS0 : sumL0) + (float)n0 * 0.125f;
            float loss1 = beta1 * (beta1 >= 0.f ? sumS1 : sumL1) + (float)n1 * 0.125f;
            float loss = (loss0 + loss1) * (loss0 + loss1);

            float lam;
            lam = beta0 * (beta0 >= 0.f ? paMin : paMax) + 0.125f; loss += lam * lam;
            lam = beta0 * (beta0 >= 0.f ? pcMin : pcMax) + 0.125f; loss += lam * lam;
            lam = beta1 * (beta1 >= 0.f ? paMin : paMax) + 0.125f; loss += lam * lam;
            lam = beta1 * (beta1 >= 0.f ? pcMin : pcMax) + 0.125f; loss += lam * lam;

            out[base + el] = loss;
        }
    }
}

extern "C" void kernel_launch(void* const* d_in, const int* in_sizes, int n_in,
                              void* d_out, int out_size)
{
    const float* rho = (const float*)d_in[0];
    const int*   r0  = (const int*)d_in[1];
    const int*   r1  = (const int*)d_in[2];
    float* out = (float*)d_out;
    int n = in_sizes[0] / 63;
    int grid = (n + EPB - 1) / EPB;
    bes_kernel<<<grid, BLK>>>(rho, r0, r1, out, n);
}

// round 9
// speedup vs baseline: 1.6933x; 1.6933x over previous
#include <cuda_runtime.h>
#include <cuda_bf16.h>

#define EPB 32                 // elements per block
#define BLK (EPB * 3)          // 3 warps: warp w handles matrix w
#define NSWEEP 4

// upper-triangle index, j<k, matches Gell-Mann sym/antisym ordering
__device__ __forceinline__ int uidx(int j, int k) {
    return j * 8 - (j * (j + 1)) / 2 + (k - j - 1);
}

__device__ __forceinline__ float rcp_approx(float x) {
    float r; asm("rcp.approx.f32 %0, %1;" : "=f"(r) : "f"(x)); return r;
}

__global__ __launch_bounds__(BLK)
void bes_kernel(const float* __restrict__ rho,
                const int* __restrict__ rank0p,
                const int* __restrict__ rank1p,
                float* __restrict__ out, int n)
{
    __shared__ float sv[EPB][65];    // staged input, padded rows
    __shared__ float ex[EPB][4];     // paMin, paMax, pcMin, pcMax exchange

    const int tid  = threadIdx.x;
    const int mat  = tid >> 5;       // warp id = matrix (0:H 1:PT_A 2:PT_C)
    const int e    = tid & 31;
    const int base = blockIdx.x * EPB;

    const int n0 = 8 - rank0p[0];
    const int n1 = 8 - rank1p[0];

    for (int i = tid; i < EPB * 63; i += BLK) {
        int t = i / 63;
        if (base + t < n) sv[t][i - t * 63] = rho[(long long)base * 63 + i];
    }
    __syncthreads();

    const float* v = sv[e];

    // --- normalize ---
    float ss = 0.f;
#pragma unroll
    for (int i = 0; i < 63; ++i) ss += v[i] * v[i];
    const float inv = rsqrtf(ss);

    // --- diagonal of H (traceless; I/8 folded out; PT preserves diagonal) ---
    const float CL1 = 1.0f, CL2 = 0.57735026919f, CL3 = 0.40824829046f,
                CL4 = 0.31622776601f, CL5 = 0.25819888975f,
                CL6 = 0.21821789023f, CL7 = 0.18898223650f;
    float f[8];
    f[0] = 0.f;
    f[1] = CL1 * v[56] * inv; f[2] = CL2 * v[57] * inv; f[3] = CL3 * v[58] * inv;
    f[4] = CL4 * v[59] * inv; f[5] = CL5 * v[60] * inv; f[6] = CL6 * v[61] * inv;
    f[7] = CL7 * v[62] * inv;
    float d8[8];
    {
        float suf = 0.f;
#pragma unroll
        for (int j = 7; j >= 0; --j) { d8[j] = suf - (float)j * f[j]; suf += f[j]; }
    }

    // --- build upper triangle: branchless PT permutation via bitmask select ---
    const int m  = (mat == 0) ? 7 : (mat == 1 ? 4 : 6);
    const int mc = 7 ^ m;
    float2 u[28];
#pragma unroll
    for (int j = 0; j < 8; ++j) {
#pragma unroll
        for (int k = j + 1; k < 8; ++k) {
            int r2 = (j & m) | (k & mc);
            int c2 = (k & m) | (j & mc);
            int rr = r2 < c2 ? r2 : c2;
            int cc = r2 < c2 ? c2 : r2;
            int m2 = uidx(rr, cc);
            float re = v[m2] * inv;
            float im = v[28 + m2] * inv;
            im = (r2 < c2) ? -im : im;
            u[uidx(j, k)] = make_float2(re, im);
        }
    }

    // --- fast-scaled cyclic complex Hermitian Jacobi ---
    // Representation: true A[j][k] = g_j g_k u~[j][k] for off-diagonals
    // (hs[k] = g_k^2, init 1); DIAGONALS d8 kept TRUE and updated exactly
    // (m +/- sv). Rotation J = T * diag(c,c) with the diag folded into hs:
    //   x~' = x~ + t_x y~,  y~' = y~ - t_y x~
    //   t_x = conj(a~) h_q / u0,  t_y = a~ h_p / u0,  u0 = delta + sv
    //   c^2 = 0.5 + 0.5 |delta| rinv (reuses rinv = rsqrt(v2))
    // 8 FFMA per free index instead of 12; chains 2-deep instead of 3.
    float hs[8];
#pragma unroll
    for (int i = 0; i < 8; ++i) hs[i] = 1.f;

#pragma unroll 1
    for (int sweep = 0; sweep < NSWEEP; ++sweep) {
#pragma unroll
        for (int p = 0; p < 8; ++p) {
#pragma unroll
            for (int q = p + 1; q < 8; ++q) {
                const int ipq = uidx(p, q);
                float2 apq = u[ipq];
                float hpq = hs[p] * hs[q];
                float b2 = (apq.x * apq.x + apq.y * apq.y) * hpq;   // true |a|^2
                float dp = d8[p], dq = d8[q];
                float delta = (dp - dq) * 0.5f;
                float mm    = (dp + dq) * 0.5f;
                float v2 = fmaf(delta, delta, b2);
                bool ok = v2 > 1e-30f;
                float rinv = rsqrtf(ok ? v2 : 1.f);
                float vv  = v2 * rinv;                  // sqrt(v2)
                float sv2 = copysignf(vv, delta);
                float u0  = delta + sv2;
                float c2  = fmaf(0.5f * fabsf(delta), rinv, 0.5f);
                c2 = ok ? c2 : 1.f;
                float rcpu = rcp_approx(u0);
                float sx = ok ? hs[q] * rcpu : 0.f;
                float sy = ok ? hs[p] * rcpu : 0.f;
                float txr =  apq.x * sx, txi = -apq.y * sx;  // t_x = conj(a~) h_q/u0
                float tyr =  apq.x * sy, tyi =  apq.y * sy;  // t_y = a~ h_p/u0
                d8[p] = mm + sv2;
                d8[q] = mm - sv2;
                hs[p] *= c2;
                hs[q] *= c2;
                u[ipq] = make_float2(0.f, 0.f);
#pragma unroll
                for (int k = 0; k < 8; ++k) {
                    if (k == p || k == q) continue;
                    float xr, xi, yr, yi;
                    if (k < p) { float2 tt = u[uidx(k, p)]; xr = tt.x; xi =  tt.y; }
                    else       { float2 tt = u[uidx(p, k)]; xr = tt.x; xi = -tt.y; }
                    if (k < q) { float2 tt = u[uidx(k, q)]; yr = tt.x; yi =  tt.y; }
                    else       { float2 tt = u[uidx(q, k)]; yr = tt.x; yi = -tt.y; }
                    float nxr = fmaf(txr, yr, fmaf(-txi, yi, xr));
                    float nxi = fmaf(txr, yi, fmaf( txi, yr, xi));
                    float nyr = fmaf(-tyr, xr, fmaf( tyi, xi, yr));
                    float nyi = fmaf(-tyr, xi, fmaf(-tyi, xr, yi));
                    if (k < p) u[uidx(k, p)] = make_float2(nxr,  nxi);
                    else       u[uidx(p, k)] = make_float2(nxr, -nxi);
                    if (k < q) u[uidx(k, q)] = make_float2(nyr,  nyi);
                    else       u[uidx(q, k)] = make_float2(nyr, -nyi);
                }
            }
        }
    }

    // --- reduce (warp-uniform branch on mat); d8 are true eigenvalues ---
    float l0 = 0.f, l7 = 0.f, sumS0 = 0.f, sumL0 = 0.f, sumS1 = 0.f, sumL1 = 0.f;
    if (mat == 0) {
#pragma unroll
        for (int i = 0; i < 7; ++i)
#pragma unroll
            for (int j = 0; j < 7 - i; ++j) {
                float lo = fminf(d8[j], d8[j + 1]);
                float hi = fmaxf(d8[j], d8[j + 1]);
                d8[j] = lo; d8[j + 1] = hi;
            }
        l0 = d8[0]; l7 = d8[7];
#pragma unroll
        for (int i = 0; i < 8; ++i) {
            if (i < n0)      sumS0 += d8[i];
            if (i >= 8 - n0) sumL0 += d8[i];
            if (i < n1)      sumS1 += d8[i];
            if (i >= 8 - n1) sumL1 += d8[i];
        }
    } else {
        float mn = d8[0], mx = d8[0];
#pragma unroll
        for (int i = 1; i < 8; ++i) { mn = fminf(mn, d8[i]); mx = fmaxf(mx, d8[i]); }
        ex[e][(mat - 1) * 2 + 0] = mn;
        ex[e][(mat - 1) * 2 + 1] = mx;
    }
    __syncthreads();

    if (mat == 0 && base + e < n) {
        float paMin = ex[e][0], paMax = ex[e][1];
        float pcMin = ex[e][2], pcMax = ex[e][3];

        const float beta0 = 1.f / (1.f - 8.f * (l0 + 0.125f));
        const float beta1 = 1.f / (1.f - 8.f * (l7 + 0.125f));

        float loss0 = beta0 * (beta0 >= 0.f ? sumS0 : sumL0) + (float)n0 * 0.125f;
        float loss1 = beta1 * (beta1 >= 0.f ? sumS1 : sumL1) + (float)n1 * 0.125f;
        float loss = (loss0 + loss1) * (loss0 + loss1);

        float lam;
        lam = beta0 * (beta0 >= 0.f ? paMin : paMax) + 0.125f; loss += lam * lam;
        lam = beta0 * (beta0 >= 0.f ? pcMin : pcMax) + 0.125f; loss += lam * lam;
        lam = beta1 * (beta1 >= 0.f ? paMin : paMax) + 0.125f; loss += lam * lam;
        lam = beta1 * (beta1 >= 0.f ? pcMin : pcMax) + 0.125f; loss += lam * lam;

        out[base + e] = loss;
    }
}

extern "C" void kernel_launch(void* const* d_in, const int* in_sizes, int n_in,
                              void* d_out, int out_size)
{
    const float* rho = (const float*)d_in[0];
    const int*   r0  = (const int*)d_in[1];
    const int*   r1  = (const int*)d_in[2];
    float* out = (float*)d_out;
    int n = in_sizes[0] / 63;
    int grid = (n + EPB - 1) / EPB;
    bes_kernel<<<grid, BLK>>>(rho, r0, r1, out, n);
}